// round 10
// baseline (speedup 1.0000x reference)
#include <cuda_runtime.h>
#include <math.h>
#include <stdint.h>

// Problem: B=64, T=1024, D=512, H=512
//   out[:,t,:] = tanh(x[:,t,:] @ Wx + b + h_{t-1} @ Wh),  h_t = out[:,t,:]
//
// R9: FULLY FUSED single persistent kernel. 16 groups x 8 CTAs
// (g = bid>>3 -> 4 batch rows, s = bid&7 -> 64 feature cols).
//   - Wh slice (512x64) in registers (64 x f32x2 pairs per thread)
//   - Wx slice (512x64) in SMEM (128 KB), x rows streamed 1 step ahead
//   - each step: xw tile computed into the accumulators FIRST (fills the
//     old poll-wait idle slots), then R7-style tagged-value h poll
//     ({f32 val, u32 tag} 8B atoms through L2, relaxed, no fences),
//     recurrent mainloop adds on top, one barrier, tree-reduce, tanh,
//     publish-then-out.
// No g_xw scratch, no separate GEMM kernel.

// [buf][group][producerCTA][feature(64)][row(4)] : {f32 val, u32 tag}
__device__ unsigned long long g_hx[2][16][8][64][4];  // 512 KB

#define FMA2(d, a, b, c) \
    asm("fma.rn.f32x2 %0, %1, %2, %3;" : "=l"(d) : "l"(a), "l"(b), "l"(c))
#define ADDF2(d, a, b) \
    asm("add.rn.f32x2 %0, %1, %2;" : "=l"(d) : "l"(a), "l"(b))
#define PACK2(d, lo, hi) \
    asm("mov.b64 %0, {%1, %2};" : "=l"(d) : "f"(lo), "f"(hi))
#define UNPACK2(lo, hi, v) \
    asm("mov.b64 {%0, %1}, %2;" : "=f"(lo), "=f"(hi) : "l"(v))

// ---------------------------------------------------------------------------
// zero the tag arena (must run each replay so stale tags never match)
// ---------------------------------------------------------------------------
__global__ void init_hx() {
    unsigned long long* p = &g_hx[0][0][0][0][0];
    int i = blockIdx.x * blockDim.x + threadIdx.x;
#pragma unroll
    for (int q = 0; q < 4; q++) p[i + q * 16384] = 0ULL;
}

// ---------------------------------------------------------------------------
// SMEM layout (dynamic, 214,016 B):
//   Wx_s [512][64]              : 32768 f  (128 KB)   xw weights
//   xdup [2][512][2][4]         :  8192 f  ( 32 KB)   x dup, double-buffered
//   hdup [8][64][2][4]          :  4096 f  ( 16 KB)   h dup per warp-chunk
//   red  u64 [2][8][4][66]      :  4224 u64 (33 KB)   k-chunk partials
// ---------------------------------------------------------------------------
static constexpr int SM_WX = 0;
static constexpr int SM_XDUP = 32768;
static constexpr int SM_HDUP = SM_XDUP + 8192;
static constexpr int SM_RED_F = SM_HDUP + 4096;  // float offset of red
static constexpr size_t SMEM_BYTES = (size_t)SM_RED_F * 4 + 4224ull * 8;

__global__ __launch_bounds__(256, 1) void rnn_fused(
    const float* __restrict__ x, const float* __restrict__ W,
    const float* __restrict__ bias, float* __restrict__ out) {
    extern __shared__ __align__(16) float sm[];
    float* const Wx_s = sm + SM_WX;
    float* const xdup = sm + SM_XDUP;
    float* const hdup = sm + SM_HDUP;
    unsigned long long* const red = (unsigned long long*)(sm + SM_RED_F);

    const int bid = blockIdx.x;
    const int g = bid >> 3;   // group 0..15
    const int r0 = g << 2;    // 4 batch rows
    const int s = bid & 7;    // col split 0..7
    const int c0 = s << 6;    // 64 feature cols
    const int tid = threadIdx.x;
    const int cp = tid & 31;  // col-pair lane
    const int ks = tid >> 5;  // warp id == k-chunk == producer CTA watched

    // ---- load Wx slice into smem (rows 0..511, cols c0..c0+63) -----------
    for (int i = tid; i < 512 * 16; i += 256) {
        int k = i >> 4;
        int cq = (i & 15) << 2;
        *(float4*)&Wx_s[k * 64 + cq] =
            *(const float4*)&W[(size_t)k * 512 + c0 + cq];
    }

    // ---- Wh slice into registers ------------------------------------------
    unsigned long long wpk[64];
#pragma unroll
    for (int j = 0; j < 64; j++) {
        float2 w2 = *(const float2*)&W[(size_t)(512 + (ks << 6) + j) * 512 +
                                       c0 + (cp << 1)];
        PACK2(wpk[j], w2.x, w2.y);
    }

    // ---- bias pair (folded into k-chunk 0's accumulators) -----------------
    unsigned long long bpk = 0ULL;
    if (ks == 0) {
        float2 b2 = *(const float2*)&bias[c0 + (cp << 1)];
        PACK2(bpk, b2.x, b2.y);
    }

    // ---- stage x(t=0) into xdup[0] ---------------------------------------
    {
        const int k0 = tid << 1;
        float2 xr[4];
#pragma unroll
        for (int r = 0; r < 4; r++) {
            xr[r] = *(const float2*)&x[((size_t)(r0 + r) * 1024 + 0) * 512 + k0];
        }
#pragma unroll
        for (int q = 0; q < 2; q++) {
            float x0 = q ? xr[0].y : xr[0].x;
            float x1 = q ? xr[1].y : xr[1].x;
            float x2 = q ? xr[2].y : xr[2].x;
            float x3 = q ? xr[3].y : xr[3].x;
            *(float4*)&xdup[(size_t)(k0 + q) * 8] = make_float4(x0, x0, x1, x1);
            *(float4*)&xdup[(size_t)(k0 + q) * 8 + 4] =
                make_float4(x2, x2, x3, x3);
        }
    }
    __syncthreads();

    const int rr = tid >> 6;  // epilogue row 0..3
    const int cc = tid & 63;  // epilogue col 0..63

    // poll sources: slots [buf][g][ks][cp][0..3] and [cp+32][0..3]
    unsigned long long* const src0 = &g_hx[0][g][ks][cp][0];
    unsigned long long* const src1 = &g_hx[0][g][ks][cp + 32][0];
    const size_t bufstride = 16 * 8 * 64 * 4;  // u64s per buffer

    // publish target: [buf][g][s][cc][rr]
    unsigned long long* const dst = &g_hx[0][g][s][cc][rr];

    float* const hd = &hdup[(ks << 6) * 8];  // this warp's 64-feature dup slab

    for (int t = 0; t < 1024; t++) {
        const int pb = t & 1;

        // ---- prefetch x(t+1): 4 x LDG.64, consumed ~1000 cyc later --------
        float2 nx[4];
        if (t < 1023) {
            const int k0 = tid << 1;
#pragma unroll
            for (int r = 0; r < 4; r++) {
                nx[r] = *(const float2*)&x[((size_t)(r0 + r) * 1024 +
                                            (size_t)(t + 1)) * 512 + k0];
            }
        }

        // ---- phase A: xw tile for step t (independent of h) ---------------
        unsigned long long a0 = bpk, a1 = bpk, a2 = bpk, a3 = bpk;
        {
            const float* xd = xdup + (size_t)pb * 512 * 8;
#pragma unroll
            for (int j = 0; j < 64; j++) {
                const int k = (ks << 6) + j;
                ulonglong2 xA = *(const ulonglong2*)(xd + (size_t)k * 8);
                ulonglong2 xB = *(const ulonglong2*)(xd + (size_t)k * 8 + 4);
                unsigned long long wv =
                    *(const unsigned long long*)&Wx_s[k * 64 + (cp << 1)];
                FMA2(a0, xA.x, wv, a0);  // row 0 {c_e,c_o}
                FMA2(a1, xA.y, wv, a1);  // row 1
                FMA2(a2, xB.x, wv, a2);  // row 2
                FMA2(a3, xB.y, wv, a3);  // row 3
            }
        }

        // ---- stage x(t+1) into the other xdup buffer ----------------------
        // (safe: every warp passed step t-1's barrier, so all reads of
        //  xdup[pb^1] from step t-1 are complete)
        if (t < 1023) {
            float* xo = xdup + (size_t)(pb ^ 1) * 512 * 8;
            const int k0 = tid << 1;
#pragma unroll
            for (int q = 0; q < 2; q++) {
                float x0 = q ? nx[0].y : nx[0].x;
                float x1 = q ? nx[1].y : nx[1].x;
                float x2 = q ? nx[2].y : nx[2].x;
                float x3 = q ? nx[3].y : nx[3].x;
                *(float4*)&xo[(size_t)(k0 + q) * 8] =
                    make_float4(x0, x0, x1, x1);
                *(float4*)&xo[(size_t)(k0 + q) * 8 + 4] =
                    make_float4(x2, x2, x3, x3);
            }
        }

        // ---- phase B: recurrent part (R7-style tagged poll) ---------------
        if (t > 0) {
            const unsigned long long* p0 = src0 + (size_t)pb * bufstride;
            const unsigned long long* p1 = src1 + (size_t)pb * bufstride;
            const unsigned int tg = (unsigned int)t;
            unsigned long long sv[8];
#pragma unroll
            for (int i = 0; i < 4; i++) {
                asm volatile("ld.relaxed.gpu.global.b64 %0, [%1];"
                             : "=l"(sv[i]) : "l"(p0 + i) : "memory");
                asm volatile("ld.relaxed.gpu.global.b64 %0, [%1];"
                             : "=l"(sv[4 + i]) : "l"(p1 + i) : "memory");
            }
            bool ok;
            do {
                ok = true;
#pragma unroll
                for (int i = 0; i < 4; i++) {
                    if ((unsigned int)(sv[i] >> 32) != tg) {
                        asm volatile("ld.relaxed.gpu.global.b64 %0, [%1];"
                                     : "=l"(sv[i]) : "l"(p0 + i) : "memory");
                        ok = false;
                    }
                    if ((unsigned int)(sv[4 + i] >> 32) != tg) {
                        asm volatile("ld.relaxed.gpu.global.b64 %0, [%1];"
                                     : "=l"(sv[4 + i]) : "l"(p1 + i)
                                     : "memory");
                        ok = false;
                    }
                }
            } while (!ok);

            // dup-expand {h0..h3} -> {h,h} broadcast form
            float h0 = __uint_as_float((unsigned int)sv[0]);
            float h1 = __uint_as_float((unsigned int)sv[1]);
            float h2 = __uint_as_float((unsigned int)sv[2]);
            float h3 = __uint_as_float((unsigned int)sv[3]);
            *(float4*)&hd[(size_t)cp * 8] = make_float4(h0, h0, h1, h1);
            *(float4*)&hd[(size_t)cp * 8 + 4] = make_float4(h2, h2, h3, h3);
            h0 = __uint_as_float((unsigned int)sv[4]);
            h1 = __uint_as_float((unsigned int)sv[5]);
            h2 = __uint_as_float((unsigned int)sv[6]);
            h3 = __uint_as_float((unsigned int)sv[7]);
            *(float4*)&hd[(size_t)(cp + 32) * 8] = make_float4(h0, h0, h1, h1);
            *(float4*)&hd[(size_t)(cp + 32) * 8 + 4] =
                make_float4(h2, h2, h3, h3);
            __syncwarp();

            // recurrent mainloop: 64 x (2 LDS.128 broadcast + 4 FFMA2)
#pragma unroll
            for (int j = 0; j < 64; j++) {
                ulonglong2 h01 = *(const ulonglong2*)(hd + (size_t)j * 8);
                ulonglong2 h23 = *(const ulonglong2*)(hd + (size_t)j * 8 + 4);
                FMA2(a0, h01.x, wpk[j], a0);
                FMA2(a1, h01.y, wpk[j], a1);
                FMA2(a2, h23.x, wpk[j], a2);
                FMA2(a3, h23.y, wpk[j], a3);
            }
        }

        // ---- cross-k-chunk reduction (double-buffered, one barrier) -------
        unsigned long long* rw = red + (size_t)((pb * 8 + ks) * 4) * 66;
        rw[0 * 66 + cp] = a0;
        rw[1 * 66 + cp] = a1;
        rw[2 * 66 + cp] = a2;
        rw[3 * 66 + cp] = a3;
        __syncthreads();

        const unsigned long long* rd =
            red + (size_t)(pb * 8) * 4 * 66 + rr * 66 + (cc >> 1);
        unsigned long long q0, q1, q2, q3;
        ADDF2(q0, rd[0 * 264], rd[1 * 264]);
        ADDF2(q1, rd[2 * 264], rd[3 * 264]);
        ADDF2(q2, rd[4 * 264], rd[5 * 264]);
        ADDF2(q3, rd[6 * 264], rd[7 * 264]);
        ADDF2(q0, q0, q1);
        ADDF2(q2, q2, q3);
        ADDF2(q0, q0, q2);
        float slo, shi;
        UNPACK2(slo, shi, q0);
        float v = tanhf(((cc & 1) ? shi : slo));

        if (t < 1023) {
            // publish tagged h FIRST — the recurrence-critical store
            unsigned long long pkt =
                ((unsigned long long)(unsigned int)(t + 1) << 32) |
                (unsigned long long)__float_as_uint(v);
            unsigned long long* d = dst + (size_t)((t + 1) & 1) * bufstride;
            asm volatile("st.relaxed.gpu.global.b64 [%0], %1;" ::"l"(d),
                         "l"(pkt)
                         : "memory");
        }
        out[((size_t)(r0 + rr) * 1024 + (size_t)t) * 512 + c0 + cc] = v;
    }
}

// ---------------------------------------------------------------------------
extern "C" void kernel_launch(void* const* d_in, const int* in_sizes, int n_in,
                              void* d_out, int out_size) {
    const float* x = (const float*)d_in[0];  // (64, 1024, 512) f32
    const float* W = (const float*)d_in[1];  // (1024, 512) f32
    const float* b = (const float*)d_in[2];  // (512,) f32
    float* out = (float*)d_out;              // (64, 1024, 512) f32

    cudaFuncSetAttribute(rnn_fused, cudaFuncAttributeMaxDynamicSharedMemorySize,
                         (int)SMEM_BYTES);
    init_hx<<<64, 256>>>();
    rnn_fused<<<128, 256, SMEM_BYTES>>>(x, W, b, out);
}

// round 11
// speedup vs baseline: 1.3300x; 1.3300x over previous
#include <cuda_runtime.h>
#include <math.h>
#include <stdint.h>

// Problem: B=64, T=1024, D=512, H=512
//   xw = x @ W[:512] + b              (65536x512x512 GEMM)
//   h_t = tanh(xw_t + h_{t-1} @ Wh)   scan over T=1024
//
// Phase 1: FFMA2 (packed f32x2) tiled GEMM -> g_xw scratch (as R7)
// Phase 2: DUAL-CHAIN interleaved scan. 128 CTAs = 16 q-slices x 8 col-CTAs.
//   CTA (q,s) runs TWO independent 2-row recurrent chains (rows 4q..4q+1 and
//   4q+2..4q+3) sharing the same Wh registers. Chain A's L2 publish latency
//   is hidden behind chain B's compute and vice versa -> polls hit on the
//   first round. Tagged {f32 val, u32 tag} 8B atoms as in R7.

__device__ float g_xw[64u * 1024u * 512u];  // 128 MB scratch: [b][t][h]
// [buf][q(16)][chain(2)][producer s(8)][feature(64)][row(2)] : {val, tag}
__device__ unsigned long long g_hx[2][16][2][8][64][2];  // 512 KB

#define FMA2(d, a, b, c) \
    asm("fma.rn.f32x2 %0, %1, %2, %3;" : "=l"(d) : "l"(a), "l"(b), "l"(c))
#define ADDF2(d, a, b) \
    asm("add.rn.f32x2 %0, %1, %2;" : "=l"(d) : "l"(a), "l"(b))
#define PACK2(d, lo, hi) \
    asm("mov.b64 %0, {%1, %2};" : "=l"(d) : "f"(lo), "f"(hi))
#define UNPACK2(lo, hi, v) \
    asm("mov.b64 {%0, %1}, %2;" : "=f"(lo), "=f"(hi) : "l"(v))

// ---------------------------------------------------------------------------
// Phase 1: g_xw[m][n] = sum_k x[m][k] * W[k][n] + b[n]   (unchanged from R7)
// ---------------------------------------------------------------------------
__global__ __launch_bounds__(256) void xw_gemm(const float* __restrict__ x,
                                               const float* __restrict__ W,
                                               const float* __restrict__ bias) {
    __shared__ __align__(16) float Ast[16][132];
    __shared__ __align__(16) float Bs[16][128];

    const int tid = threadIdx.x;
    const int bn = blockIdx.x & 3;
    const int bm = blockIdx.x >> 2;
    const int row0 = bm << 7;
    const int n0 = bn << 7;
    const int mt = tid >> 4;
    const int nt = tid & 15;

    unsigned long long acc[4][8];
#pragma unroll
    for (int p = 0; p < 4; p++)
#pragma unroll
        for (int j = 0; j < 8; j++) acc[p][j] = 0ULL;

    for (int kt = 0; kt < 512; kt += 16) {
#pragma unroll
        for (int it = 0; it < 2; it++) {
            int idx = tid + (it << 8);
            int m = idx >> 2;
            int kq = (idx & 3) << 2;
            float4 v = *(const float4*)(x + (size_t)(row0 + m) * 512 + kt + kq);
            Ast[kq + 0][m] = v.x;
            Ast[kq + 1][m] = v.y;
            Ast[kq + 2][m] = v.z;
            Ast[kq + 3][m] = v.w;
        }
#pragma unroll
        for (int it = 0; it < 2; it++) {
            int idx = tid + (it << 8);
            int k = idx >> 5;
            int nq = (idx & 31) << 2;
            *(float4*)(&Bs[k][nq]) =
                *(const float4*)(W + (size_t)(kt + k) * 512 + n0 + nq);
        }
        __syncthreads();
#pragma unroll
        for (int k = 0; k < 16; k++) {
            ulonglong2 aA = *(const ulonglong2*)(&Ast[k][4 * mt]);
            ulonglong2 aB = *(const ulonglong2*)(&Ast[k][64 + 4 * mt]);
            float4 b0 = *(const float4*)(&Bs[k][4 * nt]);
            float4 b1 = *(const float4*)(&Bs[k][64 + 4 * nt]);
            unsigned long long bb[8];
            PACK2(bb[0], b0.x, b0.x);
            PACK2(bb[1], b0.y, b0.y);
            PACK2(bb[2], b0.z, b0.z);
            PACK2(bb[3], b0.w, b0.w);
            PACK2(bb[4], b1.x, b1.x);
            PACK2(bb[5], b1.y, b1.y);
            PACK2(bb[6], b1.z, b1.z);
            PACK2(bb[7], b1.w, b1.w);
#pragma unroll
            for (int j = 0; j < 8; j++) {
                FMA2(acc[0][j], aA.x, bb[j], acc[0][j]);
                FMA2(acc[1][j], aA.y, bb[j], acc[1][j]);
                FMA2(acc[2][j], aB.x, bb[j], acc[2][j]);
                FMA2(acc[3][j], aB.y, bb[j], acc[3][j]);
            }
        }
        __syncthreads();
    }

    float bv[8];
#pragma unroll
    for (int j = 0; j < 4; j++) {
        bv[j] = bias[n0 + 4 * nt + j];
        bv[4 + j] = bias[n0 + 64 + 4 * nt + j];
    }
    float res[8][8];
#pragma unroll
    for (int p = 0; p < 4; p++)
#pragma unroll
        for (int j = 0; j < 8; j++) {
            float lo, hi;
            UNPACK2(lo, hi, acc[p][j]);
            res[2 * p][j] = lo + bv[j];
            res[2 * p + 1][j] = hi + bv[j];
        }
#pragma unroll
    for (int rI = 0; rI < 8; rI++) {
        int lrow = (rI < 4) ? (4 * mt + rI) : (64 + 4 * mt + (rI - 4));
        size_t base = (size_t)(row0 + lrow) * 512 + n0;
        float4 s0 = make_float4(res[rI][0], res[rI][1], res[rI][2], res[rI][3]);
        float4 s1 = make_float4(res[rI][4], res[rI][5], res[rI][6], res[rI][7]);
        *(float4*)(g_xw + base + 4 * nt) = s0;
        *(float4*)(g_xw + base + 64 + 4 * nt) = s1;
    }
}

// ---------------------------------------------------------------------------
// zero the tag arena (each replay, so stale tags never match)
// ---------------------------------------------------------------------------
__global__ void init_hx() {
    unsigned long long* p = &g_hx[0][0][0][0][0][0];
    int i = blockIdx.x * blockDim.x + threadIdx.x;
#pragma unroll
    for (int q = 0; q < 4; q++) p[i + q * 16384] = 0ULL;
}

// ---------------------------------------------------------------------------
// Phase 2: dual-chain interleaved scan.
// ---------------------------------------------------------------------------
__global__ __launch_bounds__(256, 1) void rnn_scan(const float* __restrict__ W,
                                                   float* __restrict__ out) {
    __shared__ __align__(16) float hdup[8][64][4];            // 8 KB
    __shared__ __align__(16) unsigned long long redA[8][2][33];  // 4.2 KB
    __shared__ __align__(16) unsigned long long redB[8][2][33];  // 4.2 KB

    const int bid = blockIdx.x;
    const int q = bid >> 3;   // q-slice 0..15  -> rows 4q..4q+3
    const int s = bid & 7;    // col split 0..7 -> cols 64s..64s+63
    const int c0 = s << 6;
    const int tid = threadIdx.x;
    const int cp = tid & 31;  // col-pair lane
    const int ks = tid >> 5;  // warp id == k-chunk == producer CTA watched

    // Wh slice: wpk[j] = {W[512+64ks+j][c0+2cp], W[512+64ks+j][c0+2cp+1]}
    unsigned long long wpk[64];
#pragma unroll
    for (int j = 0; j < 64; j++) {
        float2 w2 = *(const float2*)&W[(size_t)(512 + (ks << 6) + j) * 512 +
                                       c0 + (cp << 1)];
        PACK2(wpk[j], w2.x, w2.y);
    }

    // epilogue role: warps 0-3 -> chain A outputs, warps 4-7 -> chain B
    const int echain = tid >> 7;           // 0 = A, 1 = B
    const int err_ = (tid >> 6) & 1;       // row within chain 0..1
    const int ecc = tid & 63;              // col 0..63
    const int erow = (q << 2) + (echain << 1) + err_;  // global batch row

    const size_t bufstride = 16 * 2 * 8 * 64 * 2;  // u64 per buffer (32768)

    // poll bases for this warp (chain A and B), buffer 0
    unsigned long long* const pollA = &g_hx[0][q][0][ks][0][0];
    unsigned long long* const pollB = &g_hx[0][q][1][ks][0][0];
    // publish target for this thread's epilogue output
    unsigned long long* const dst = &g_hx[0][q][echain][s][ecc][err_];

    float* const hd = &hdup[ks][0][0];

    for (int t = 0; t < 1024; t++) {
        const int pb = t & 1;
        const unsigned int tg = (unsigned int)t;

        // xw prefetch for this thread's epilogue output (A or B)
        float xwv =
            g_xw[((size_t)erow * 1024 + (size_t)t) * 512 + c0 + ecc];

        // =================== chain A ======================================
        unsigned long long a0 = 0ULL, a1 = 0ULL;
        if (t > 0) {
            const unsigned long long* p = pollA + (size_t)pb * bufstride;
            // lane cp: feat cp rows{0,1} at [2cp,2cp+1]; feat cp+32 likewise
            unsigned long long sv[4];
            asm volatile("ld.relaxed.gpu.global.b64 %0, [%1];"
                         : "=l"(sv[0]) : "l"(p + (cp << 1)) : "memory");
            asm volatile("ld.relaxed.gpu.global.b64 %0, [%1];"
                         : "=l"(sv[1]) : "l"(p + (cp << 1) + 1) : "memory");
            asm volatile("ld.relaxed.gpu.global.b64 %0, [%1];"
                         : "=l"(sv[2]) : "l"(p + ((cp + 32) << 1)) : "memory");
            asm volatile("ld.relaxed.gpu.global.b64 %0, [%1];"
                         : "=l"(sv[3]) : "l"(p + ((cp + 32) << 1) + 1)
                         : "memory");
            bool ok;
            do {
                ok = true;
                if ((unsigned int)(sv[0] >> 32) != tg) {
                    asm volatile("ld.relaxed.gpu.global.b64 %0, [%1];"
                                 : "=l"(sv[0]) : "l"(p + (cp << 1)) : "memory");
                    ok = false;
                }
                if ((unsigned int)(sv[1] >> 32) != tg) {
                    asm volatile("ld.relaxed.gpu.global.b64 %0, [%1];"
                                 : "=l"(sv[1]) : "l"(p + (cp << 1) + 1)
                                 : "memory");
                    ok = false;
                }
                if ((unsigned int)(sv[2] >> 32) != tg) {
                    asm volatile("ld.relaxed.gpu.global.b64 %0, [%1];"
                                 : "=l"(sv[2]) : "l"(p + ((cp + 32) << 1))
                                 : "memory");
                    ok = false;
                }
                if ((unsigned int)(sv[3] >> 32) != tg) {
                    asm volatile("ld.relaxed.gpu.global.b64 %0, [%1];"
                                 : "=l"(sv[3]) : "l"(p + ((cp + 32) << 1) + 1)
                                 : "memory");
                    ok = false;
                }
            } while (!ok);

            float h0 = __uint_as_float((unsigned int)sv[0]);
            float h1 = __uint_as_float((unsigned int)sv[1]);
            *(float4*)&hdup[ks][cp][0] = make_float4(h0, h0, h1, h1);
            h0 = __uint_as_float((unsigned int)sv[2]);
            h1 = __uint_as_float((unsigned int)sv[3]);
            *(float4*)&hdup[ks][cp + 32][0] = make_float4(h0, h0, h1, h1);
            __syncwarp();

#pragma unroll
            for (int j = 0; j < 64; j++) {
                ulonglong2 h01 = *(const ulonglong2*)(hd + (j << 2));
                FMA2(a0, h01.x, wpk[j], a0);  // row 0 {c_e,c_o}
                FMA2(a1, h01.y, wpk[j], a1);  // row 1
            }
            __syncwarp();  // hd reads done before chain B overwrites
        }
        redA[ks][0][cp] = a0;
        redA[ks][1][cp] = a1;
        __syncthreads();

        // chain A epilogue (warps 0-3)
        if (echain == 0) {
            unsigned long long q0, q1, q2, q3;
            ADDF2(q0, redA[0][err_][ecc >> 1], redA[1][err_][ecc >> 1]);
            ADDF2(q1, redA[2][err_][ecc >> 1], redA[3][err_][ecc >> 1]);
            ADDF2(q2, redA[4][err_][ecc >> 1], redA[5][err_][ecc >> 1]);
            ADDF2(q3, redA[6][err_][ecc >> 1], redA[7][err_][ecc >> 1]);
            ADDF2(q0, q0, q1);
            ADDF2(q2, q2, q3);
            ADDF2(q0, q0, q2);
            float slo, shi;
            UNPACK2(slo, shi, q0);
            float v = tanhf(xwv + ((ecc & 1) ? shi : slo));
            if (t < 1023) {
                unsigned long long pkt =
                    ((unsigned long long)(tg + 1) << 32) |
                    (unsigned long long)__float_as_uint(v);
                unsigned long long* d =
                    dst + (size_t)((t + 1) & 1) * bufstride;
                asm volatile("st.relaxed.gpu.global.b64 [%0], %1;" ::"l"(d),
                             "l"(pkt)
                             : "memory");
            }
            out[((size_t)erow * 1024 + (size_t)t) * 512 + c0 + ecc] = v;
        }

        // =================== chain B ======================================
        unsigned long long b0 = 0ULL, b1 = 0ULL;
        if (t > 0) {
            const unsigned long long* p = pollB + (size_t)pb * bufstride;
            unsigned long long sv[4];
            asm volatile("ld.relaxed.gpu.global.b64 %0, [%1];"
                         : "=l"(sv[0]) : "l"(p + (cp << 1)) : "memory");
            asm volatile("ld.relaxed.gpu.global.b64 %0, [%1];"
                         : "=l"(sv[1]) : "l"(p + (cp << 1) + 1) : "memory");
            asm volatile("ld.relaxed.gpu.global.b64 %0, [%1];"
                         : "=l"(sv[2]) : "l"(p + ((cp + 32) << 1)) : "memory");
            asm volatile("ld.relaxed.gpu.global.b64 %0, [%1];"
                         : "=l"(sv[3]) : "l"(p + ((cp + 32) << 1) + 1)
                         : "memory");
            bool ok;
            do {
                ok = true;
                if ((unsigned int)(sv[0] >> 32) != tg) {
                    asm volatile("ld.relaxed.gpu.global.b64 %0, [%1];"
                                 : "=l"(sv[0]) : "l"(p + (cp << 1)) : "memory");
                    ok = false;
                }
                if ((unsigned int)(sv[1] >> 32) != tg) {
                    asm volatile("ld.relaxed.gpu.global.b64 %0, [%1];"
                                 : "=l"(sv[1]) : "l"(p + (cp << 1) + 1)
                                 : "memory");
                    ok = false;
                }
                if ((unsigned int)(sv[2] >> 32) != tg) {
                    asm volatile("ld.relaxed.gpu.global.b64 %0, [%1];"
                                 : "=l"(sv[2]) : "l"(p + ((cp + 32) << 1))
                                 : "memory");
                    ok = false;
                }
                if ((unsigned int)(sv[3] >> 32) != tg) {
                    asm volatile("ld.relaxed.gpu.global.b64 %0, [%1];"
                                 : "=l"(sv[3]) : "l"(p + ((cp + 32) << 1) + 1)
                                 : "memory");
                    ok = false;
                }
            } while (!ok);

            float h0 = __uint_as_float((unsigned int)sv[0]);
            float h1 = __uint_as_float((unsigned int)sv[1]);
            *(float4*)&hdup[ks][cp][0] = make_float4(h0, h0, h1, h1);
            h0 = __uint_as_float((unsigned int)sv[2]);
            h1 = __uint_as_float((unsigned int)sv[3]);
            *(float4*)&hdup[ks][cp + 32][0] = make_float4(h0, h0, h1, h1);
            __syncwarp();

#pragma unroll
            for (int j = 0; j < 64; j++) {
                ulonglong2 h01 = *(const ulonglong2*)(hd + (j << 2));
                FMA2(b0, h01.x, wpk[j], b0);
                FMA2(b1, h01.y, wpk[j], b1);
            }
        }
        redB[ks][0][cp] = b0;
        redB[ks][1][cp] = b1;
        __syncthreads();

        // chain B epilogue (warps 4-7)
        if (echain == 1) {
            unsigned long long q0, q1, q2, q3;
            ADDF2(q0, redB[0][err_][ecc >> 1], redB[1][err_][ecc >> 1]);
            ADDF2(q1, redB[2][err_][ecc >> 1], redB[3][err_][ecc >> 1]);
            ADDF2(q2, redB[4][err_][ecc >> 1], redB[5][err_][ecc >> 1]);
            ADDF2(q3, redB[6][err_][ecc >> 1], redB[7][err_][ecc >> 1]);
            ADDF2(q0, q0, q1);
            ADDF2(q2, q2, q3);
            ADDF2(q0, q0, q2);
            float slo, shi;
            UNPACK2(slo, shi, q0);
            float v = tanhf(xwv + ((ecc & 1) ? shi : slo));
            if (t < 1023) {
                unsigned long long pkt =
                    ((unsigned long long)(tg + 1) << 32) |
                    (unsigned long long)__float_as_uint(v);
                unsigned long long* d =
                    dst + (size_t)((t + 1) & 1) * bufstride;
                asm volatile("st.relaxed.gpu.global.b64 [%0], %1;" ::"l"(d),
                             "l"(pkt)
                             : "memory");
            }
            out[((size_t)erow * 1024 + (size_t)t) * 512 + c0 + ecc] = v;
        }
    }
}

// ---------------------------------------------------------------------------
extern "C" void kernel_launch(void* const* d_in, const int* in_sizes, int n_in,
                              void* d_out, int out_size) {
    const float* x = (const float*)d_in[0];  // (64, 1024, 512) f32
    const float* W = (const float*)d_in[1];  // (1024, 512) f32
    const float* b = (const float*)d_in[2];  // (512,) f32
    float* out = (float*)d_out;              // (64, 1024, 512) f32

    xw_gemm<<<2048, 256>>>(x, W, b);
    init_hx<<<64, 256>>>();
    rnn_scan<<<128, 256>>>(W, out);
}

// round 14
// speedup vs baseline: 1.4411x; 1.0836x over previous
#include <cuda_runtime.h>
#include <cuda_bf16.h>
#include <math.h>
#include <stdint.h>

// Problem: B=64, T=1024, D=512, H=512
//   xw = x @ W[:512] + b              (65536x512x512 GEMM)
//   h_t = tanh(xw_t + h_{t-1} @ Wh)   scan over T=1024
//
// Phase 1: split-bf16 GEMM on legacy tensor path (mma.sync m16n8k16 —
//   tcgen05 is unavailable: harness PTX target is sm_103 without 'a').
//   xw ~= xh@wh + xl@wh + xh@wl, fp32 accumulate.
// Phase 2: EXACT R7 scan (best known): tagged {f32 val, u32 tag} 8B atoms
//   through L2, relaxed, no fences; 16 groups x 8 CTAs.

__device__ float g_xw[64u * 1024u * 512u];  // 128 MB scratch: [b][t][h]
// [buf][group][producerCTA][feature(64)][row(4)] : {f32 val, u32 tag}
__device__ unsigned long long g_hx[2][16][8][64][4];  // 512 KB

#define FMA2(d, a, b, c) \
    asm("fma.rn.f32x2 %0, %1, %2, %3;" : "=l"(d) : "l"(a), "l"(b), "l"(c))
#define ADDF2(d, a, b) \
    asm("add.rn.f32x2 %0, %1, %2;" : "=l"(d) : "l"(a), "l"(b))
#define PACK2(d, lo, hi) \
    asm("mov.b64 %0, {%1, %2};" : "=l"(d) : "f"(lo), "f"(hi))
#define UNPACK2(lo, hi, v) \
    asm("mov.b64 {%0, %1}, %2;" : "=f"(lo), "=f"(hi) : "l"(v))

static __device__ __forceinline__ uint32_t smem_u32(const void* p) {
    uint32_t a;
    asm("{ .reg .u64 t; cvta.to.shared.u64 t, %1; cvt.u32.u64 %0, t; }"
        : "=r"(a) : "l"(p));
    return a;
}

// ===========================================================================
// Phase 1: split-bf16 mma.sync GEMM
// ===========================================================================
#define LDM4(r, addr) \
    asm volatile("ldmatrix.sync.aligned.m8n8.x4.shared.b16 {%0,%1,%2,%3}, [%4];" \
                 : "=r"((r)[0]), "=r"((r)[1]), "=r"((r)[2]), "=r"((r)[3]) \
                 : "r"(addr))
#define LDM2T(r, addr) \
    asm volatile("ldmatrix.sync.aligned.m8n8.x2.trans.shared.b16 {%0,%1}, [%2];" \
                 : "=r"((r)[0]), "=r"((r)[1]) \
                 : "r"(addr))
#define MMA16816(d, a, b) \
    asm volatile( \
        "mma.sync.aligned.m16n8k16.row.col.f32.bf16.bf16.f32 " \
        "{%0,%1,%2,%3}, {%4,%5,%6,%7}, {%8,%9}, {%0,%1,%2,%3};" \
        : "+f"((d)[0]), "+f"((d)[1]), "+f"((d)[2]), "+f"((d)[3]) \
        : "r"((a)[0]), "r"((a)[1]), "r"((a)[2]), "r"((a)[3]), \
          "r"((b)[0]), "r"((b)[1]))

static __device__ __forceinline__ void cvt_split4(float4 v, uint2& hh,
                                                  uint2& ll) {
    __nv_bfloat16 h0 = __float2bfloat16(v.x);
    __nv_bfloat16 h1 = __float2bfloat16(v.y);
    __nv_bfloat16 h2 = __float2bfloat16(v.z);
    __nv_bfloat16 h3 = __float2bfloat16(v.w);
    __nv_bfloat16 l0 = __float2bfloat16(v.x - __bfloat162float(h0));
    __nv_bfloat16 l1 = __float2bfloat16(v.y - __bfloat162float(h1));
    __nv_bfloat16 l2 = __float2bfloat16(v.z - __bfloat162float(h2));
    __nv_bfloat16 l3 = __float2bfloat16(v.w - __bfloat162float(h3));
    hh.x = (uint32_t)__bfloat16_as_ushort(h0) |
           ((uint32_t)__bfloat16_as_ushort(h1) << 16);
    hh.y = (uint32_t)__bfloat16_as_ushort(h2) |
           ((uint32_t)__bfloat16_as_ushort(h3) << 16);
    ll.x = (uint32_t)__bfloat16_as_ushort(l0) |
           ((uint32_t)__bfloat16_as_ushort(l1) << 16);
    ll.y = (uint32_t)__bfloat16_as_ushort(l2) |
           ((uint32_t)__bfloat16_as_ushort(l3) << 16);
}

// smem row strides (in b16 units) chosen conflict-free for ldmatrix
static constexpr int A_STR = 40;    // 32 k + 8 pad
static constexpr int B_STR = 136;   // 128 n + 8 pad

__global__ __launch_bounds__(256, 1) void xw_mma(const float* __restrict__ x,
                                                 const float* __restrict__ W,
                                                 const float* __restrict__ bias) {
    __shared__ __align__(16) uint16_t Ah[128 * A_STR];
    __shared__ __align__(16) uint16_t Al[128 * A_STR];
    __shared__ __align__(16) uint16_t Bh[32 * B_STR];
    __shared__ __align__(16) uint16_t Bl[32 * B_STR];

    const int tid = threadIdx.x;
    const int wid = tid >> 5;
    const int lane = tid & 31;
    const int wm = wid >> 2;  // 0..1 -> 64 rows
    const int wn = wid & 3;   // 0..3 -> 32 cols
    const int row0 = (blockIdx.x >> 2) << 7;
    const int n0 = (blockIdx.x & 3) << 7;

    const uint32_t sAh = smem_u32(Ah);
    const uint32_t sAl = smem_u32(Al);
    const uint32_t sBh = smem_u32(Bh);
    const uint32_t sBl = smem_u32(Bl);

    // ldmatrix lane address offsets
    const int arow = (lane & 7) + ((lane >> 3) & 1) * 8;  // row within 16
    const int acol = (lane >> 4) << 3;                    // 0 or 8
    const uint32_t aoff = (uint32_t)(((wm * 64 + arow) * A_STR + acol) * 2);
    const int l4 = lane & 15;                             // B k-row 0..15
    const uint32_t boff = (uint32_t)((l4 * B_STR + wn * 32) * 2);

    float d[4][4][4];
#pragma unroll
    for (int mt = 0; mt < 4; mt++)
#pragma unroll
        for (int nt = 0; nt < 4; nt++)
#pragma unroll
            for (int i = 0; i < 4; i++) d[mt][nt][i] = 0.0f;

    for (int kt = 0; kt < 512; kt += 32) {
        // ---- fill A (128 rows x 32 k): hi/lo bf16 ----------------------
#pragma unroll
        for (int it = 0; it < 4; it++) {
            const int idx = tid + (it << 8);
            const int row = idx >> 3;
            const int kq = (idx & 7) << 2;
            float4 v = *(const float4*)&x[(size_t)(row0 + row) * 512 + kt + kq];
            uint2 hh, ll;
            cvt_split4(v, hh, ll);
            *(uint2*)&Ah[row * A_STR + kq] = hh;
            *(uint2*)&Al[row * A_STR + kq] = ll;
        }
        // ---- fill B (32 k x 128 n): hi/lo bf16 -------------------------
#pragma unroll
        for (int it = 0; it < 4; it++) {
            const int idx = tid + (it << 8);
            const int k = idx >> 5;
            const int n4 = (idx & 31) << 2;
            float4 v = *(const float4*)&W[(size_t)(kt + k) * 512 + n0 + n4];
            uint2 hh, ll;
            cvt_split4(v, hh, ll);
            *(uint2*)&Bh[k * B_STR + n4] = hh;
            *(uint2*)&Bl[k * B_STR + n4] = ll;
        }
        __syncthreads();

        // ---- compute: 2 x k16 ------------------------------------------
#pragma unroll
        for (int kk = 0; kk < 32; kk += 16) {
            uint32_t ah[4][4], al[4][4], bh[4][2], bl[4][2];
#pragma unroll
            for (int mt = 0; mt < 4; mt++) {
                const uint32_t ao = aoff + (uint32_t)(mt * 16 * A_STR * 2 + kk * 2);
                LDM4(ah[mt], sAh + ao);
                LDM4(al[mt], sAl + ao);
            }
#pragma unroll
            for (int nt = 0; nt < 4; nt++) {
                const uint32_t bo = boff + (uint32_t)(nt * 16 + kk * B_STR * 2);
                LDM2T(bh[nt], sBh + bo);
                LDM2T(bl[nt], sBl + bo);
            }
#pragma unroll
            for (int mt = 0; mt < 4; mt++) {
#pragma unroll
                for (int nt = 0; nt < 4; nt++) {
                    MMA16816(d[mt][nt], ah[mt], bh[nt]);
                    MMA16816(d[mt][nt], al[mt], bh[nt]);
                    MMA16816(d[mt][nt], ah[mt], bl[nt]);
                }
            }
        }
        __syncthreads();
    }

    // ---- epilogue: add bias, store fp32 --------------------------------
    const int g4 = lane >> 2;
    const int l2 = (lane & 3) << 1;
#pragma unroll
    for (int nt = 0; nt < 4; nt++) {
        const int col = n0 + wn * 32 + nt * 8 + l2;
        float2 bv = *(const float2*)&bias[col];
#pragma unroll
        for (int mt = 0; mt < 4; mt++) {
            const int r = row0 + wm * 64 + mt * 16 + g4;
            float2 o0, o1;
            o0.x = d[mt][nt][0] + bv.x;
            o0.y = d[mt][nt][1] + bv.y;
            o1.x = d[mt][nt][2] + bv.x;
            o1.y = d[mt][nt][3] + bv.y;
            *(float2*)&g_xw[(size_t)r * 512 + col] = o0;
            *(float2*)&g_xw[(size_t)(r + 8) * 512 + col] = o1;
        }
    }
}

// ===========================================================================
// zero the tag arena (each replay, so stale tags never match)
// ===========================================================================
__global__ void init_hx() {
    unsigned long long* p = &g_hx[0][0][0][0][0];
    int i = blockIdx.x * blockDim.x + threadIdx.x;
#pragma unroll
    for (int q = 0; q < 4; q++) p[i + q * 16384] = 0ULL;
}

// ===========================================================================
// Phase 2: EXACT R7 tagged-value scan (best known)
// ===========================================================================
__global__ __launch_bounds__(256, 1) void rnn_scan(const float* __restrict__ W,
                                                   float* __restrict__ out) {
    __shared__ __align__(16) float dupA[8][64][4];                 // 8 KB
    __shared__ __align__(16) float dupB[8][64][4];                 // 8 KB
    __shared__ __align__(16) unsigned long long red[2][8][4][66];  // 33 KB

    const int bid = blockIdx.x;
    const int g = bid >> 3;   // group 0..15
    const int r0 = g << 2;    // 4 batch rows
    const int s = bid & 7;    // col split 0..7
    const int c0 = s << 6;    // 64 feature cols
    const int tid = threadIdx.x;
    const int cp = tid & 31;  // col-pair lane
    const int ks = tid >> 5;  // warp id == producer CTA watched

    unsigned long long wpk[64];
#pragma unroll
    for (int j = 0; j < 64; j++) {
        float2 w2 = *(const float2*)&W[(size_t)(512 + (ks << 6) + j) * 512 +
                                       c0 + (cp << 1)];
        PACK2(wpk[j], w2.x, w2.y);
    }

    const int rr = tid >> 6;  // epilogue row 0..3
    const int cc = tid & 63;  // epilogue col 0..63

    unsigned long long* const src0 = &g_hx[0][g][ks][cp][0];
    unsigned long long* const src1 = &g_hx[0][g][ks][cp + 32][0];
    const size_t bufstride = 16 * 8 * 64 * 4;

    unsigned long long* const dst = &g_hx[0][g][s][cc][rr];

    for (int t = 0; t < 1024; t++) {
        const int pb = t & 1;
        float xwv =
            g_xw[((size_t)(r0 + rr) * 1024 + (size_t)t) * 512 + c0 + cc];

        unsigned long long a0 = 0ULL, a1 = 0ULL, a2 = 0ULL, a3 = 0ULL;
        if (t > 0) {
            const unsigned long long* p0 = src0 + (size_t)pb * bufstride;
            const unsigned long long* p1 = src1 + (size_t)pb * bufstride;
            const unsigned int tg = (unsigned int)t;
            unsigned long long sv[8];
#pragma unroll
            for (int i = 0; i < 4; i++) {
                asm volatile("ld.relaxed.gpu.global.b64 %0, [%1];"
                             : "=l"(sv[i]) : "l"(p0 + i) : "memory");
                asm volatile("ld.relaxed.gpu.global.b64 %0, [%1];"
                             : "=l"(sv[4 + i]) : "l"(p1 + i) : "memory");
            }
            bool ok;
            do {
                ok = true;
#pragma unroll
                for (int i = 0; i < 4; i++) {
                    if ((unsigned int)(sv[i] >> 32) != tg) {
                        asm volatile("ld.relaxed.gpu.global.b64 %0, [%1];"
                                     : "=l"(sv[i]) : "l"(p0 + i) : "memory");
                        ok = false;
                    }
                    if ((unsigned int)(sv[4 + i] >> 32) != tg) {
                        asm volatile("ld.relaxed.gpu.global.b64 %0, [%1];"
                                     : "=l"(sv[4 + i]) : "l"(p1 + i)
                                     : "memory");
                        ok = false;
                    }
                }
            } while (!ok);

            float h0 = __uint_as_float((unsigned int)sv[0]);
            float h1 = __uint_as_float((unsigned int)sv[1]);
            float h2 = __uint_as_float((unsigned int)sv[2]);
            float h3 = __uint_as_float((unsigned int)sv[3]);
            *(float4*)&dupA[ks][cp][0] = make_float4(h0, h0, h1, h1);
            *(float4*)&dupB[ks][cp][0] = make_float4(h2, h2, h3, h3);
            h0 = __uint_as_float((unsigned int)sv[4]);
            h1 = __uint_as_float((unsigned int)sv[5]);
            h2 = __uint_as_float((unsigned int)sv[6]);
            h3 = __uint_as_float((unsigned int)sv[7]);
            *(float4*)&dupA[ks][cp + 32][0] = make_float4(h0, h0, h1, h1);
            *(float4*)&dupB[ks][cp + 32][0] =
                make_float4(h2, h2, h3, h3);
            __syncwarp();

            float* const hdA = &dupA[ks][0][0];
            float* const hdB = &dupB[ks][0][0];
#pragma unroll
            for (int j = 0; j < 64; j++) {
                ulonglong2 h01 = *(const ulonglong2*)(hdA + (j << 2));
                ulonglong2 h23 = *(const ulonglong2*)(hdB + (j << 2));
                FMA2(a0, h01.x, wpk[j], a0);
                FMA2(a1, h01.y, wpk[j], a1);
                FMA2(a2, h23.x, wpk[j], a2);
                FMA2(a3, h23.y, wpk[j], a3);
            }
        }
        red[pb][ks][0][cp] = a0;
        red[pb][ks][1][cp] = a1;
        red[pb][ks][2][cp] = a2;
        red[pb][ks][3][cp] = a3;
        __syncthreads();

        unsigned long long q0, q1, q2, q3;
        ADDF2(q0, red[pb][0][rr][cc >> 1], red[pb][1][rr][cc >> 1]);
        ADDF2(q1, red[pb][2][rr][cc >> 1], red[pb][3][rr][cc >> 1]);
        ADDF2(q2, red[pb][4][rr][cc >> 1], red[pb][5][rr][cc >> 1]);
        ADDF2(q3, red[pb][6][rr][cc >> 1], red[pb][7][rr][cc >> 1]);
        ADDF2(q0, q0, q1);
        ADDF2(q2, q2, q3);
        ADDF2(q0, q0, q2);
        float slo, shi;
        UNPACK2(slo, shi, q0);
        float v = tanhf(xwv + ((cc & 1) ? shi : slo));

        if (t < 1023) {
            unsigned long long pkt =
                ((unsigned long long)(unsigned int)(t + 1) << 32) |
                (unsigned long long)__float_as_uint(v);
            unsigned long long* d2 = dst + (size_t)((t + 1) & 1) * bufstride;
            asm volatile("st.relaxed.gpu.global.b64 [%0], %1;" ::"l"(d2),
                         "l"(pkt)
                         : "memory");
        }
        out[((size_t)(r0 + rr) * 1024 + (size_t)t) * 512 + c0 + cc] = v;
    }
}

// ---------------------------------------------------------------------------
extern "C" void kernel_launch(void* const* d_in, const int* in_sizes, int n_in,
                              void* d_out, int out_size) {
    const float* x = (const float*)d_in[0];  // (64, 1024, 512) f32
    const float* W = (const float*)d_in[1];  // (1024, 512) f32
    const float* b = (const float*)d_in[2];  // (512,) f32
    float* out = (float*)d_out;              // (64, 1024, 512) f32

    xw_mma<<<2048, 256>>>(x, W, b);
    init_hx<<<64, 256>>>();
    rnn_scan<<<128, 256>>>(W, out);
}

// round 16
// speedup vs baseline: 1.4897x; 1.0337x over previous
#include <cuda_runtime.h>
#include <cuda_bf16.h>
#include <math.h>
#include <stdint.h>

// Problem: B=64, T=1024, D=512, H=512
//   xw = x @ W[:512] + b              (65536x512x512 GEMM)
//   h_t = tanh(xw_t + h_{t-1} @ Wh)   scan over T=1024
//
// Phase 1: split-bf16 GEMM on legacy tensor path (mma.sync m16n8k16),
//   R15: register-prefetch software pipeline — next k-tile's fp32 loads
//   issue before the current tile's MMAs, hiding gmem latency.
//   xw ~= xh@wh + xl@wh + xh@wl, fp32 accumulate.
// Phase 2: EXACT R7 scan (best known): tagged {f32 val, u32 tag} 8B atoms
//   through L2, relaxed, no fences; 16 groups x 8 CTAs.

__device__ float g_xw[64u * 1024u * 512u];  // 128 MB scratch: [b][t][h]
// [buf][group][producerCTA][feature(64)][row(4)] : {f32 val, u32 tag}
__device__ unsigned long long g_hx[2][16][8][64][4];  // 512 KB

#define FMA2(d, a, b, c) \
    asm("fma.rn.f32x2 %0, %1, %2, %3;" : "=l"(d) : "l"(a), "l"(b), "l"(c))
#define ADDF2(d, a, b) \
    asm("add.rn.f32x2 %0, %1, %2;" : "=l"(d) : "l"(a), "l"(b))
#define PACK2(d, lo, hi) \
    asm("mov.b64 %0, {%1, %2};" : "=l"(d) : "f"(lo), "f"(hi))
#define UNPACK2(lo, hi, v) \
    asm("mov.b64 {%0, %1}, %2;" : "=f"(lo), "=f"(hi) : "l"(v))

static __device__ __forceinline__ uint32_t smem_u32(const void* p) {
    uint32_t a;
    asm("{ .reg .u64 t; cvta.to.shared.u64 t, %1; cvt.u32.u64 %0, t; }"
        : "=r"(a) : "l"(p));
    return a;
}

// ===========================================================================
// Phase 1: split-bf16 mma.sync GEMM (pipelined)
// ===========================================================================
#define LDM4(r, addr) \
    asm volatile("ldmatrix.sync.aligned.m8n8.x4.shared.b16 {%0,%1,%2,%3}, [%4];" \
                 : "=r"((r)[0]), "=r"((r)[1]), "=r"((r)[2]), "=r"((r)[3]) \
                 : "r"(addr))
#define LDM2T(r, addr) \
    asm volatile("ldmatrix.sync.aligned.m8n8.x2.trans.shared.b16 {%0,%1}, [%2];" \
                 : "=r"((r)[0]), "=r"((r)[1]) \
                 : "r"(addr))
#define MMA16816(d, a, b) \
    asm volatile( \
        "mma.sync.aligned.m16n8k16.row.col.f32.bf16.bf16.f32 " \
        "{%0,%1,%2,%3}, {%4,%5,%6,%7}, {%8,%9}, {%0,%1,%2,%3};" \
        : "+f"((d)[0]), "+f"((d)[1]), "+f"((d)[2]), "+f"((d)[3]) \
        : "r"((a)[0]), "r"((a)[1]), "r"((a)[2]), "r"((a)[3]), \
          "r"((b)[0]), "r"((b)[1]))

static __device__ __forceinline__ void cvt_split4(float4 v, uint2& hh,
                                                  uint2& ll) {
    __nv_bfloat16 h0 = __float2bfloat16(v.x);
    __nv_bfloat16 h1 = __float2bfloat16(v.y);
    __nv_bfloat16 h2 = __float2bfloat16(v.z);
    __nv_bfloat16 h3 = __float2bfloat16(v.w);
    __nv_bfloat16 l0 = __float2bfloat16(v.x - __bfloat162float(h0));
    __nv_bfloat16 l1 = __float2bfloat16(v.y - __bfloat162float(h1));
    __nv_bfloat16 l2 = __float2bfloat16(v.z - __bfloat162float(h2));
    __nv_bfloat16 l3 = __float2bfloat16(v.w - __bfloat162float(h3));
    hh.x = (uint32_t)__bfloat16_as_ushort(h0) |
           ((uint32_t)__bfloat16_as_ushort(h1) << 16);
    hh.y = (uint32_t)__bfloat16_as_ushort(h2) |
           ((uint32_t)__bfloat16_as_ushort(h3) << 16);
    ll.x = (uint32_t)__bfloat16_as_ushort(l0) |
           ((uint32_t)__bfloat16_as_ushort(l1) << 16);
    ll.y = (uint32_t)__bfloat16_as_ushort(l2) |
           ((uint32_t)__bfloat16_as_ushort(l3) << 16);
}

// smem row strides (in b16 units) chosen conflict-free for ldmatrix
static constexpr int A_STR = 40;    // 32 k + 8 pad
static constexpr int B_STR = 136;   // 128 n + 8 pad

__global__ __launch_bounds__(256, 1) void xw_mma(const float* __restrict__ x,
                                                 const float* __restrict__ W,
                                                 const float* __restrict__ bias) {
    __shared__ __align__(16) uint16_t Ah[128 * A_STR];
    __shared__ __align__(16) uint16_t Al[128 * A_STR];
    __shared__ __align__(16) uint16_t Bh[32 * B_STR];
    __shared__ __align__(16) uint16_t Bl[32 * B_STR];

    const int tid = threadIdx.x;
    const int wid = tid >> 5;
    const int lane = tid & 31;
    const int wm = wid >> 2;  // 0..1 -> 64 rows
    const int wn = wid & 3;   // 0..3 -> 32 cols
    const int row0 = (blockIdx.x >> 2) << 7;
    const int n0 = (blockIdx.x & 3) << 7;

    const uint32_t sAh = smem_u32(Ah);
    const uint32_t sAl = smem_u32(Al);
    const uint32_t sBh = smem_u32(Bh);
    const uint32_t sBl = smem_u32(Bl);

    // per-thread fill coordinates (fixed across tiles)
    const int a_row = tid >> 1;          // 0..127  (2 threads per row)
    const int a_kq = (tid & 1) << 4;     // 0 or 16 -> 4 float4 each? no:
    // A tile is 128 rows x 32 k fp32 = 16KB = 16 float4-loads per row.
    // Use: 4 iters, idx = tid + it*256; row = idx>>3, kq = (idx&7)*4.
    const int l4 = lane & 15;
    const int arow = (lane & 7) + ((lane >> 3) & 1) * 8;
    const int acol = (lane >> 4) << 3;
    const uint32_t aoff = (uint32_t)(((wm * 64 + arow) * A_STR + acol) * 2);
    const uint32_t boff = (uint32_t)((l4 * B_STR + wn * 32) * 2);
    (void)a_row; (void)a_kq;

    float d[4][4][4];
#pragma unroll
    for (int mt = 0; mt < 4; mt++)
#pragma unroll
        for (int nt = 0; nt < 4; nt++)
#pragma unroll
            for (int i = 0; i < 4; i++) d[mt][nt][i] = 0.0f;

    float4 pa[4], pb[4];

    // ---- preload tile kt=0 into registers ------------------------------
#pragma unroll
    for (int it = 0; it < 4; it++) {
        const int idx = tid + (it << 8);
        pa[it] = *(const float4*)&x[(size_t)(row0 + (idx >> 3)) * 512 +
                                    ((idx & 7) << 2)];
        pb[it] = *(const float4*)&W[(size_t)(idx >> 5) * 512 + n0 +
                                    ((idx & 31) << 2)];
    }
    // convert + store tile 0
#pragma unroll
    for (int it = 0; it < 4; it++) {
        const int idx = tid + (it << 8);
        uint2 hh, ll;
        cvt_split4(pa[it], hh, ll);
        *(uint2*)&Ah[(idx >> 3) * A_STR + ((idx & 7) << 2)] = hh;
        *(uint2*)&Al[(idx >> 3) * A_STR + ((idx & 7) << 2)] = ll;
        cvt_split4(pb[it], hh, ll);
        *(uint2*)&Bh[(idx >> 5) * B_STR + ((idx & 31) << 2)] = hh;
        *(uint2*)&Bl[(idx >> 5) * B_STR + ((idx & 31) << 2)] = ll;
    }
    __syncthreads();

    for (int kt = 0; kt < 512; kt += 32) {
        // ---- prefetch NEXT tile's fp32 into registers (latency hidden
        //      behind this tile's MMAs) --------------------------------
        const bool have_next = (kt + 32) < 512;
        if (have_next) {
#pragma unroll
            for (int it = 0; it < 4; it++) {
                const int idx = tid + (it << 8);
                pa[it] = *(const float4*)&x[(size_t)(row0 + (idx >> 3)) * 512 +
                                            kt + 32 + ((idx & 7) << 2)];
                pb[it] = *(const float4*)&W[(size_t)(kt + 32 + (idx >> 5)) * 512 +
                                            n0 + ((idx & 31) << 2)];
            }
        }

        // ---- compute current tile: 2 x k16 -----------------------------
#pragma unroll
        for (int kk = 0; kk < 32; kk += 16) {
            uint32_t ah[4][4], al[4][4], bh[4][2], bl[4][2];
#pragma unroll
            for (int mt = 0; mt < 4; mt++) {
                const uint32_t ao = aoff + (uint32_t)(mt * 16 * A_STR * 2 + kk * 2);
                LDM4(ah[mt], sAh + ao);
                LDM4(al[mt], sAl + ao);
            }
#pragma unroll
            for (int nt = 0; nt < 4; nt++) {
                const uint32_t bo = boff + (uint32_t)(nt * 16 + kk * B_STR * 2);
                LDM2T(bh[nt], sBh + bo);
                LDM2T(bl[nt], sBl + bo);
            }
#pragma unroll
            for (int mt = 0; mt < 4; mt++) {
#pragma unroll
                for (int nt = 0; nt < 4; nt++) {
                    MMA16816(d[mt][nt], ah[mt], bh[nt]);
                    MMA16816(d[mt][nt], al[mt], bh[nt]);
                    MMA16816(d[mt][nt], ah[mt], bl[nt]);
                }
            }
        }
        __syncthreads();  // all smem reads of this tile complete

        if (have_next) {
            // ---- convert + store next tile ------------------------------
#pragma unroll
            for (int it = 0; it < 4; it++) {
                const int idx = tid + (it << 8);
                uint2 hh, ll;
                cvt_split4(pa[it], hh, ll);
                *(uint2*)&Ah[(idx >> 3) * A_STR + ((idx & 7) << 2)] = hh;
                *(uint2*)&Al[(idx >> 3) * A_STR + ((idx & 7) << 2)] = ll;
                cvt_split4(pb[it], hh, ll);
                *(uint2*)&Bh[(idx >> 5) * B_STR + ((idx & 31) << 2)] = hh;
                *(uint2*)&Bl[(idx >> 5) * B_STR + ((idx & 31) << 2)] = ll;
            }
            __syncthreads();
        }
    }

    // ---- epilogue: add bias, store fp32 --------------------------------
    const int g4 = lane >> 2;
    const int l2 = (lane & 3) << 1;
#pragma unroll
    for (int nt = 0; nt < 4; nt++) {
        const int col = n0 + wn * 32 + nt * 8 + l2;
        float2 bv = *(const float2*)&bias[col];
#pragma unroll
        for (int mt = 0; mt < 4; mt++) {
            const int r = row0 + wm * 64 + mt * 16 + g4;
            float2 o0, o1;
            o0.x = d[mt][nt][0] + bv.x;
            o0.y = d[mt][nt][1] + bv.y;
            o1.x = d[mt][nt][2] + bv.x;
            o1.y = d[mt][nt][3] + bv.y;
            *(float2*)&g_xw[(size_t)r * 512 + col] = o0;
            *(float2*)&g_xw[(size_t)(r + 8) * 512 + col] = o1;
        }
    }
}

// ===========================================================================
// zero the tag arena (each replay, so stale tags never match)
// ===========================================================================
__global__ void init_hx() {
    unsigned long long* p = &g_hx[0][0][0][0][0];
    int i = blockIdx.x * blockDim.x + threadIdx.x;
#pragma unroll
    for (int q = 0; q < 4; q++) p[i + q * 16384] = 0ULL;
}

// ===========================================================================
// Phase 2: EXACT R7 tagged-value scan (best known)
// ===========================================================================
__global__ __launch_bounds__(256, 1) void rnn_scan(const float* __restrict__ W,
                                                   float* __restrict__ out) {
    __shared__ __align__(16) float dupA[8][64][4];                 // 8 KB
    __shared__ __align__(16) float dupB[8][64][4];                 // 8 KB
    __shared__ __align__(16) unsigned long long red[2][8][4][66];  // 33 KB

    const int bid = blockIdx.x;
    const int g = bid >> 3;   // group 0..15
    const int r0 = g << 2;    // 4 batch rows
    const int s = bid & 7;    // col split 0..7
    const int c0 = s << 6;    // 64 feature cols
    const int tid = threadIdx.x;
    const int cp = tid & 31;  // col-pair lane
    const int ks = tid >> 5;  // warp id == producer CTA watched

    unsigned long long wpk[64];
#pragma unroll
    for (int j = 0; j < 64; j++) {
        float2 w2 = *(const float2*)&W[(size_t)(512 + (ks << 6) + j) * 512 +
                                       c0 + (cp << 1)];
        PACK2(wpk[j], w2.x, w2.y);
    }

    const int rr = tid >> 6;  // epilogue row 0..3
    const int cc = tid & 63;  // epilogue col 0..63

    unsigned long long* const src0 = &g_hx[0][g][ks][cp][0];
    unsigned long long* const src1 = &g_hx[0][g][ks][cp + 32][0];
    const size_t bufstride = 16 * 8 * 64 * 4;

    unsigned long long* const dst = &g_hx[0][g][s][cc][rr];

    for (int t = 0; t < 1024; t++) {
        const int pb = t & 1;
        float xwv =
            g_xw[((size_t)(r0 + rr) * 1024 + (size_t)t) * 512 + c0 + cc];

        unsigned long long a0 = 0ULL, a1 = 0ULL, a2 = 0ULL, a3 = 0ULL;
        if (t > 0) {
            const unsigned long long* p0 = src0 + (size_t)pb * bufstride;
            const unsigned long long* p1 = src1 + (size_t)pb * bufstride;
            const unsigned int tg = (unsigned int)t;
            unsigned long long sv[8];
#pragma unroll
            for (int i = 0; i < 4; i++) {
                asm volatile("ld.relaxed.gpu.global.b64 %0, [%1];"
                             : "=l"(sv[i]) : "l"(p0 + i) : "memory");
                asm volatile("ld.relaxed.gpu.global.b64 %0, [%1];"
                             : "=l"(sv[4 + i]) : "l"(p1 + i) : "memory");
            }
            bool ok;
            do {
                ok = true;
#pragma unroll
                for (int i = 0; i < 4; i++) {
                    if ((unsigned int)(sv[i] >> 32) != tg) {
                        asm volatile("ld.relaxed.gpu.global.b64 %0, [%1];"
                                     : "=l"(sv[i]) : "l"(p0 + i) : "memory");
                        ok = false;
                    }
                    if ((unsigned int)(sv[4 + i] >> 32) != tg) {
                        asm volatile("ld.relaxed.gpu.global.b64 %0, [%1];"
                                     : "=l"(sv[4 + i]) : "l"(p1 + i)
                                     : "memory");
                        ok = false;
                    }
                }
            } while (!ok);

            float h0 = __uint_as_float((unsigned int)sv[0]);
            float h1 = __uint_as_float((unsigned int)sv[1]);
            float h2 = __uint_as_float((unsigned int)sv[2]);
            float h3 = __uint_as_float((unsigned int)sv[3]);
            *(float4*)&dupA[ks][cp][0] = make_float4(h0, h0, h1, h1);
            *(float4*)&dupB[ks][cp][0] = make_float4(h2, h2, h3, h3);
            h0 = __uint_as_float((unsigned int)sv[4]);
            h1 = __uint_as_float((unsigned int)sv[5]);
            h2 = __uint_as_float((unsigned int)sv[6]);
            h3 = __uint_as_float((unsigned int)sv[7]);
            *(float4*)&dupA[ks][cp + 32][0] = make_float4(h0, h0, h1, h1);
            *(float4*)&dupB[ks][cp + 32][0] =
                make_float4(h2, h2, h3, h3);
            __syncwarp();

            float* const hdA = &dupA[ks][0][0];
            float* const hdB = &dupB[ks][0][0];
#pragma unroll
            for (int j = 0; j < 64; j++) {
                ulonglong2 h01 = *(const ulonglong2*)(hdA + (j << 2));
                ulonglong2 h23 = *(const ulonglong2*)(hdB + (j << 2));
                FMA2(a0, h01.x, wpk[j], a0);
                FMA2(a1, h01.y, wpk[j], a1);
                FMA2(a2, h23.x, wpk[j], a2);
                FMA2(a3, h23.y, wpk[j], a3);
            }
        }
        red[pb][ks][0][cp] = a0;
        red[pb][ks][1][cp] = a1;
        red[pb][ks][2][cp] = a2;
        red[pb][ks][3][cp] = a3;
        __syncthreads();

        unsigned long long q0, q1, q2, q3;
        ADDF2(q0, red[pb][0][rr][cc >> 1], red[pb][1][rr][cc >> 1]);
        ADDF2(q1, red[pb][2][rr][cc >> 1], red[pb][3][rr][cc >> 1]);
        ADDF2(q2, red[pb][4][rr][cc >> 1], red[pb][5][rr][cc >> 1]);
        ADDF2(q3, red[pb][6][rr][cc >> 1], red[pb][7][rr][cc >> 1]);
        ADDF2(q0, q0, q1);
        ADDF2(q2, q2, q3);
        ADDF2(q0, q0, q2);
        float slo, shi;
        UNPACK2(slo, shi, q0);
        float v = tanhf(xwv + ((cc & 1) ? shi : slo));

        if (t < 1023) {
            unsigned long long pkt =
                ((unsigned long long)(unsigned int)(t + 1) << 32) |
                (unsigned long long)__float_as_uint(v);
            unsigned long long* d2 = dst + (size_t)((t + 1) & 1) * bufstride;
            asm volatile("st.relaxed.gpu.global.b64 [%0], %1;" ::"l"(d2),
                         "l"(pkt)
                         : "memory");
        }
        out[((size_t)(r0 + rr) * 1024 + (size_t)t) * 512 + c0 + cc] = v;
    }
}

// ---------------------------------------------------------------------------
extern "C" void kernel_launch(void* const* d_in, const int* in_sizes, int n_in,
                              void* d_out, int out_size) {
    const float* x = (const float*)d_in[0];  // (64, 1024, 512) f32
    const float* W = (const float*)d_in[1];  // (1024, 512) f32
    const float* b = (const float*)d_in[2];  // (512,) f32
    float* out = (float*)d_out;              // (64, 1024, 512) f32

    xw_mma<<<2048, 256>>>(x, W, b);
    init_hx<<<64, 256>>>();
    rnn_scan<<<128, 256>>>(W, out);
}